// round 12
// baseline (speedup 1.0000x reference)
#include <cuda_runtime.h>
#include <math.h>

#define BSZ  8
#define KPS  8
#define NPK  16
#define TT   3072
#define WGW  64
#define HHH  256
#define WCC  256
#define RHH  1024
#define RWW  512
#define MM   64          // BSZ*KPS

#define C1H 1024
#define C1W 31
#define C2H 341
#define C2W 15
#define C3H 113
#define C3W 7

#define N1  (MM*C1H*C1W)     // 2031616
#define N2  (MM*C2H*C2W)     // 327360 per channel
#define N3  (MM*C3H*C3W)     // 50624
#define NF  (BSZ*RHH*RWW)    // 4194304

#define TROWS 16             // output rows per tile in the final stage
#define NSLOT 64             // reduction slots (contention spreading)

// conv1 tiling
#define S1ROWS 32
#define S1IN   (3*S1ROWS)    // 96
#define NS1    (C1H/S1ROWS)  // 32

// conv2 tiling
#define R2   22
#define NS2  16
#define TR2  (3*R2 + 4)      // 70

// ---------------- scratch (device globals; no allocation) ----------------
__device__ unsigned int g_pmax[NSLOT];
__device__ double g_ps1[NSLOT], g_pq1[NSLOT];
__device__ double g_ps2[2][NSLOT], g_pq2[2][NSLOT];
__device__ double g_ps3[NSLOT], g_pq3[NSLOT];
__device__ double g_psf[NSLOT], g_pqf[NSLOT];

__device__ float g_conv1[N1];
__device__ float g_conv2[2*N2];
__device__ float g_conv3[N3];
__device__ float g_genr[MM*RHH];
__device__ int   g_vint[MM*HHH];
__device__ float g_yraw[NF];

// ---------------- helpers ----------------
__device__ __forceinline__ float lrelu(float x){ return x >= 0.f ? x : 0.1f*x; }

__device__ __forceinline__ float warpSumF(float v){
#pragma unroll
    for (int o = 16; o > 0; o >>= 1) v += __shfl_down_sync(0xffffffffu, v, o);
    return v;
}
__device__ __forceinline__ float warpMaxF(float v){
#pragma unroll
    for (int o = 16; o > 0; o >>= 1) v = fmaxf(v, __shfl_down_sync(0xffffffffu, v, o));
    return v;
}
__device__ __forceinline__ double warpAllSumD(double v){
#pragma unroll
    for (int o = 16; o > 0; o >>= 1) v += __shfl_xor_sync(0xffffffffu, v, o);
    return v;
}
__device__ __forceinline__ unsigned warpAllMaxU(unsigned v){
#pragma unroll
    for (int o = 16; o > 0; o >>= 1){
        unsigned u = __shfl_xor_sync(0xffffffffu, v, o);
        v = (u > v) ? u : v;
    }
    return v;
}

// block reduce (a,b) floats -> double atomics into slot (blockIdx & 63)
__device__ __forceinline__ void blockRedSlot2(float a, float b, double* da, double* db){
    a = warpSumF(a); b = warpSumF(b);
    __shared__ double sa[8], sb[8];
    int lane = threadIdx.x & 31, w = threadIdx.x >> 5;
    int nw = blockDim.x >> 5;
    if (lane == 0){ sa[w] = (double)a; sb[w] = (double)b; }
    __syncthreads();
    if (w == 0){
        double x = (lane < nw) ? sa[lane] : 0.0;
        double y = (lane < nw) ? sb[lane] : 0.0;
#pragma unroll
        for (int o = 4; o > 0; o >>= 1){
            x += __shfl_down_sync(0xffffffffu, x, o);
            y += __shfl_down_sync(0xffffffffu, y, o);
        }
        if (lane == 0){
            int slot = blockIdx.x & (NSLOT-1);
            atomicAdd(&da[slot], x); atomicAdd(&db[slot], y);
        }
    }
    __syncthreads();
}

// warp 0 all-reduce of 64 double slots (call from threads of warp 0 only)
__device__ __forceinline__ double sumSlots(const double* slots, int lane){
    double v = slots[lane] + slots[lane + 32];
    return warpAllSumD(v);
}

// ---------------- kernels ----------------
__global__ void k_init(){
    int t = threadIdx.x;
    if (t < NSLOT){
        g_pmax[t] = 0u;
        g_ps1[t] = 0; g_pq1[t] = 0;
        g_ps2[0][t] = 0; g_ps2[1][t] = 0;
        g_pq2[0][t] = 0; g_pq2[1][t] = 0;
        g_ps3[t] = 0; g_pq3[t] = 0;
        g_psf[t] = 0; g_pqf[t] = 0;
    }
}

// smem-tiled conv1 RAW + maxabs + stats. Block = image m x 32-output-row strip.
__global__ void __launch_bounds__(256) k_conv1(const float* __restrict__ g,
                                               const float* __restrict__ w1){
    __shared__ float s_in[S1IN][WGW];   // 24 KB

    int m     = blockIdx.x >> 5;
    int strip = blockIdx.x & 31;
    int i0    = strip * S1ROWS;
    int tid   = threadIdx.x;

    const float4* src = (const float4*)(g + (size_t)m*(TT*WGW) + (size_t)(3*i0)*WGW);

    float mx = 0.f;
#pragma unroll
    for (int k = 0; k < (S1IN*16)/256; k++){
        int idx = tid + k*256;
        float4 v = src[idx];
        int row = idx >> 4, c4 = idx & 15;
        s_in[row][c4*4+0] = v.x;
        s_in[row][c4*4+1] = v.y;
        s_in[row][c4*4+2] = v.z;
        s_in[row][c4*4+3] = v.w;
        mx = fmaxf(mx, fmaxf(fmaxf(fabsf(v.x), fabsf(v.y)), fmaxf(fabsf(v.z), fabsf(v.w))));
    }
    __syncthreads();

    float w[9];
#pragma unroll
    for (int p = 0; p < 9; p++) w[p] = __ldg(&w1[p]);

    float s = 0.f, q = 0.f;
    for (int o = tid; o < S1ROWS*C1W; o += 256){
        int oi = o / C1W, j = o % C1W;
        int r0 = 3*oi, c0 = 2*j;
        float acc = 0.f;
#pragma unroll
        for (int p = 0; p < 3; p++){
            acc += w[p*3+0]*s_in[r0+p][c0]
                 + w[p*3+1]*s_in[r0+p][c0+1]
                 + w[p*3+2]*s_in[r0+p][c0+2];
        }
        g_conv1[((size_t)m*C1H + i0 + oi)*C1W + j] = acc;
        s += acc; q += acc*acc;
    }

    {
        float mm = warpMaxF(mx);
        __shared__ float sm[8];
        int lane = threadIdx.x & 31, wp = threadIdx.x >> 5;
        if (lane == 0) sm[wp] = mm;
        __syncthreads();
        if (wp == 0){
            mm = (lane < 8) ? sm[lane] : 0.f;
            mm = warpMaxF(mm);
            if (lane == 0)
                atomicMax(&g_pmax[blockIdx.x & (NSLOT-1)], __float_as_uint(mm));
        }
        __syncthreads();
    }
    blockRedSlot2(s, q, g_ps1, g_pq1);
}

// smem-tiled conv2 (separable pooling). warp 0 reduces slot stats for BN1.
__global__ void __launch_bounds__(256) k_conv2(const float* __restrict__ w2,
                                               const float* __restrict__ b2,
                                               const float* __restrict__ g1,
                                               const float* __restrict__ be1){
    __shared__ float s_act[TR2][36];
    __shared__ float s_rm3[TR2][32];
    __shared__ float s_rm5[TR2][32];
    __shared__ float s_ab[2];

    int m     = blockIdx.x >> 4;
    int strip = blockIdx.x & 15;
    int i0    = strip * R2;
    int nout  = min(R2, C2H - i0);
    int tid   = threadIdx.x;

    if (tid < 32){
        double s1 = sumSlots(g_ps1, tid);
        double q1 = sumSlots(g_pq1, tid);
        unsigned mb = g_pmax[tid];
        unsigned mb2 = g_pmax[tid + 32];
        mb = (mb2 > mb) ? mb2 : mb;
        mb = warpAllMaxU(mb);
        if (tid == 0){
            double inv  = 1.0 / (double)__uint_as_float(mb);
            double mc   = s1 / (double)N1;
            double varc = q1 / (double)N1 - mc*mc;
            double istd = 1.0 / sqrt(inv*inv*varc + 1e-5);
            double A = inv*istd*(double)g1[0];
            s_ab[0] = (float)A;
            s_ab[1] = (float)((double)be1[0] - A*mc);
        }
    }
    for (int lr = tid; lr < TR2; lr += 256){
        s_act[lr][0] = -1e30f; s_act[lr][1] = -1e30f;
        s_act[lr][33] = -1e30f; s_act[lr][34] = -1e30f;
    }
    __syncthreads();
    float A1 = s_ab[0], B1 = s_ab[1];

    int gr0 = 3*i0 - 2;
    const float* src = g_conv1 + (size_t)m*(C1H*C1W);
    for (int idx = tid; idx < TR2*C1W; idx += 256){
        int lr = idx / C1W, c = idx % C1W;
        int gr = gr0 + lr;
        float v = -1e30f;
        if (gr >= 0 && gr < C1H)
            v = lrelu(src[gr*C1W + c]*A1 + B1);
        s_act[lr][c+2] = v;
    }
    __syncthreads();

    for (int idx = tid; idx < TR2*C1W; idx += 256){
        int lr = idx / C1W, c = idx % C1W;
        float a0 = s_act[lr][c],   a1 = s_act[lr][c+1], a2 = s_act[lr][c+2];
        float a3 = s_act[lr][c+3], a4 = s_act[lr][c+4];
        s_rm3[lr][c] = fmaxf(a1, fmaxf(a2, a3));
        s_rm5[lr][c] = fmaxf(fmaxf(a0, a1), fmaxf(a2, fmaxf(a3, a4)));
    }
    __syncthreads();

    float w[54];
#pragma unroll
    for (int p = 0; p < 54; p++) w[p] = __ldg(&w2[p]);
    float bb0 = __ldg(&b2[0]), bb1 = __ldg(&b2[1]);

    float s0 = 0.f, q0 = 0.f, s1 = 0.f, q1 = 0.f;
    for (int o = tid; o < nout*C2W; o += 256){
        int oi = o / C2W, j = o % C2W;
        float acc0 = bb0, acc1 = bb1;
#pragma unroll
        for (int p = 0; p < 3; p++){
            int lr = 3*oi + p + 2;
#pragma unroll
            for (int qq = 0; qq < 3; qq++){
                int c = 2*j + qq;
                float v0 = s_act[lr][c+2];
                float p3 = fmaxf(s_rm3[lr-1][c], fmaxf(s_rm3[lr][c], s_rm3[lr+1][c]));
                float p5 = fmaxf(fmaxf(s_rm5[lr-2][c], s_rm5[lr-1][c]),
                                 fmaxf(s_rm5[lr][c], fmaxf(s_rm5[lr+1][c], s_rm5[lr+2][c])));
                int off = p*3 + qq;
                acc0 += w[off]*v0    + w[9+off]*p3  + w[18+off]*p5;
                acc1 += w[27+off]*v0 + w[36+off]*p3 + w[45+off]*p5;
            }
        }
        int i = i0 + oi;
        g_conv2[((m*2+0)*C2H + i)*C2W + j] = acc0;
        g_conv2[((m*2+1)*C2H + i)*C2W + j] = acc1;
        s0 += acc0; q0 += acc0*acc0;
        s1 += acc1; q1 += acc1*acc1;
    }
    blockRedSlot2(s0, q0, g_ps2[0], g_pq2[0]);
    blockRedSlot2(s1, q1, g_ps2[1], g_pq2[1]);
}

// conv3: per-output, 128 threads; warps 0/1 reduce the two channel stats
__global__ void __launch_bounds__(128) k_conv3(const float* __restrict__ w3,
                                               const float* __restrict__ b3,
                                               const float* __restrict__ g2,
                                               const float* __restrict__ be2){
    __shared__ float s_ab[4];
    if (threadIdx.x < 64){
        int c = threadIdx.x >> 5;
        int lane = threadIdx.x & 31;
        double s = sumSlots(g_ps2[c], lane);
        double q = sumSlots(g_pq2[c], lane);
        if (lane == 0){
            double mn = s / (double)N2;
            double vr = q / (double)N2 - mn*mn;
            double sc = (double)g2[c] / sqrt(vr + 1e-5);
            s_ab[c]   = (float)sc;
            s_ab[2+c] = (float)((double)be2[c] - mn*sc);
        }
    }
    __syncthreads();

    int idx = blockIdx.x*blockDim.x + threadIdx.x;
    float s = 0, q = 0;
    if (idx < N3){
        int j = idx % C3W; int t = idx / C3W; int i = t % C3H; int m = t / C3H;
        float acc = b3[0];
#pragma unroll
        for (int c = 0; c < 2; c++){
            float A2 = s_ab[c], B2 = s_ab[2+c];
            const float* B = g_conv2 + ((m*2+c)*C2H)*C2W;
#pragma unroll
            for (int p = 0; p < 3; p++){
#pragma unroll
                for (int qq = 0; qq < 2; qq++){
                    float raw = B[(3*i+p)*C2W + 2*j+qq];
                    acc += w3[c*6 + p*2 + qq]*lrelu(raw*A2 + B2);
                }
            }
        }
        g_conv3[idx] = acc;
        s = acc; q = acc*acc;
    }
    blockRedSlot2(s, q, g_ps3, g_pq3);
}

// fused rowval + genr + vint: 4 blocks per image
__global__ void __launch_bounds__(256) k_mid(const float* __restrict__ cv,
                                             const float* __restrict__ VMM,
                                             const float* __restrict__ g3,
                                             const float* __restrict__ be3){
    __shared__ float s_rv[C3H];
    __shared__ float s_ab[2];
    int m   = blockIdx.x >> 2;
    int qtr = blockIdx.x & 3;
    int tid = threadIdx.x;

    if (tid < 32){
        double s = sumSlots(g_ps3, tid);
        double q = sumSlots(g_pq3, tid);
        if (tid == 0){
            double mn = s / (double)N3;
            double vr = q / (double)N3 - mn*mn;
            double sc = (double)g3[0] / sqrt(vr + 1e-5);
            s_ab[0] = (float)sc;
            s_ab[1] = (float)((double)be3[0] - mn*sc);
        }
    }
    __syncthreads();
    float A3 = s_ab[0], B3 = s_ab[1];

    if (tid < C3H){
        const float wcol[7] = {4.f/37.f, 5.f/37.f, 6.f/37.f, 7.f/37.f, 6.f/37.f, 5.f/37.f, 4.f/37.f};
        const float* B = g_conv3 + (m*C3H + tid)*C3W;
        float rv = 0.f;
#pragma unroll
        for (int j = 0; j < 7; j++)
            rv += wcol[j] * lrelu(B[j]*A3 + B3);
        s_rv[tid] = rv;
    }

    if (qtr == 0){
        int b = m / KPS;
        const float* C = cv + m*NPK*2;
        const float dt = 7000.0f/255.0f;
        float vm0 = VMM[b*2];
        float dv = (VMM[b*2+1] - vm0)/255.0f;
        float tq = (float)tid;
        float tp = C[0]/dt, vp = (C[1] - vm0)/dv;
        float val;
        if (tq <= tp){
            val = vp;
        } else {
            val = (C[2*(NPK-1)+1] - vm0)/dv;
            for (int n = 1; n < NPK; n++){
                float tn = C[2*n]/dt, vn = (C[2*n+1] - vm0)/dv;
                if (tq <= tn){ val = vp + (vn - vp)*(tq - tp)/(tn - tp); break; }
                tp = tn; vp = vn;
            }
        }
        int vi = (int)val;
        g_vint[m*HHH + tid] = min(WCC-1, max(0, vi));
    }
    __syncthreads();

    int rh = qtr*256 + tid;
    float ih = (rh + 0.5f)*(113.0f/1024.0f) - 0.5f;
    ih = fminf(fmaxf(ih, 0.f), 112.f);
    int h0 = (int)ih; float f = ih - (float)h0;
    int h1 = min(h0 + 1, 112);
    g_genr[m*RHH + rh] = (1.f - f)*s_rv[h0] + f*s_rv[h1];
}

// sparse scatter of one source column v with weight w into mix row
__device__ __forceinline__ void scatter_src(float* row, int v, float w){
    if (w == 0.f) return;
    if (v == 0){
        atomicAdd(&row[0], w);
        atomicAdd(&row[1], 0.75f*w);
        atomicAdd(&row[2], 0.25f*w);
    } else if (v == 255){
        atomicAdd(&row[509], 0.25f*w);
        atomicAdd(&row[510], 0.75f*w);
        atomicAdd(&row[511], w);
    } else {
        atomicAdd(&row[2*v-1], 0.25f*w);
        atomicAdd(&row[2*v  ], 0.75f*w);
        atomicAdd(&row[2*v+1], 0.75f*w);
        atomicAdd(&row[2*v+2], 0.25f*w);
    }
}

// fused mix (sparse) + conv_f: raw y + stats
__global__ void __launch_bounds__(256) k_statsF(const float* __restrict__ wf,
                                                const float* __restrict__ bf){
    __shared__ float s_mix[TROWS+2][RWW];
    __shared__ float s_g[TROWS+2][8];
    __shared__ float s_w0[TROWS+2][8];
    __shared__ float s_w1[TROWS+2][8];
    __shared__ int   s_v0[TROWS+2][8];
    __shared__ int   s_v1[TROWS+2][8];
    __shared__ float s_base[TROWS+2];

    int b   = blockIdx.x / (RHH/TROWS);
    int rh0 = (blockIdx.x % (RHH/TROWS)) * TROWS;
    int tid = threadIdx.x;

    if (tid < (TROWS+2)*8){
        int r = tid >> 3, k = tid & 7;
        int gr = rh0 - 1 + r;
        float g = 0.f, fh = 0.f; int v0 = 0, v1 = 0;
        if (gr >= 0 && gr < RHH){
            float ih = (gr + 0.5f)*0.25f - 0.5f;
            ih = fminf(fmaxf(ih, 0.f), 255.f);
            int h0 = (int)ih; fh = ih - (float)h0; int h1 = min(h0 + 1, 255);
            int m = b*KPS + k;
            g  = g_genr[m*RHH + gr];
            v0 = g_vint[m*HHH + h0];
            v1 = g_vint[m*HHH + h1];
        }
        s_g[r][k] = g;
        s_w0[r][k] = 0.9f*g*(1.f - fh);
        s_w1[r][k] = 0.9f*g*fh;
        s_v0[r][k] = v0; s_v1[r][k] = v1;
    }
    __syncthreads();

    if (tid < TROWS+2){
        float s = 0.f;
#pragma unroll
        for (int k = 0; k < 8; k++) s += s_g[tid][k];
        s_base[tid] = 0.01f*s;
    }
    __syncthreads();

    for (int idx = tid; idx < (TROWS+2)*RWW; idx += 256){
        int r = idx >> 9, c = idx & 511;
        s_mix[r][c] = s_base[r];
    }
    __syncthreads();

    if (tid < (TROWS+2)*8){
        int r = tid >> 3, k = tid & 7;
        scatter_src(&s_mix[r][0], s_v0[r][k], s_w0[r][k]);
        scatter_src(&s_mix[r][0], s_v1[r][k], s_w1[r][k]);
    }
    __syncthreads();

    float W[9];
#pragma unroll
    for (int i = 0; i < 9; i++) W[i] = __ldg(&wf[i]);
    float bb = __ldg(&bf[0]);

    float s = 0.f, q = 0.f;
    for (int orow = 0; orow < TROWS; orow++){
#pragma unroll
        for (int half = 0; half < 2; half++){
            int c = tid + half*256;
            float acc = bb;
#pragma unroll
            for (int p = 0; p < 3; p++){
#pragma unroll
                for (int qq = 0; qq < 3; qq++){
                    int cc = c - 1 + qq;
                    if (cc >= 0 && cc < RWW)
                        acc += W[p*3+qq]*s_mix[orow+p][cc];
                }
            }
            g_yraw[((size_t)b*RHH + rh0 + orow)*RWW + c] = acc;
            s += acc; q += acc*acc;
        }
    }
    blockRedSlot2(s, q, g_psf, g_pqf);
}

// elementwise: out = lrelu(yraw*sc + sh), float4
__global__ void __launch_bounds__(256) k_final(const float* __restrict__ gf,
                                               const float* __restrict__ bef,
                                               float* __restrict__ out){
    __shared__ float s_ab[2];
    if (threadIdx.x < 32){
        double s = sumSlots(g_psf, threadIdx.x);
        double q = sumSlots(g_pqf, threadIdx.x);
        if (threadIdx.x == 0){
            double mn = s / (double)NF;
            double vr = q / (double)NF - mn*mn;
            double sc = (double)gf[0] / sqrt(vr + 1e-5);
            s_ab[0] = (float)sc;
            s_ab[1] = (float)((double)bef[0] - mn*sc);
        }
    }
    __syncthreads();
    float sc = s_ab[0], sh = s_ab[1];

    int i = blockIdx.x*blockDim.x + threadIdx.x;
    if (i < NF/4){
        float4 y = ((const float4*)g_yraw)[i];
        float4 o;
        o.x = lrelu(y.x*sc + sh);
        o.y = lrelu(y.y*sc + sh);
        o.z = lrelu(y.z*sc + sh);
        o.w = lrelu(y.w*sc + sh);
        ((float4*)out)[i] = o;
    }
}

// ---------------- launch ----------------
extern "C" void kernel_launch(void* const* d_in, const int* in_sizes, int n_in,
                              void* d_out, int out_size){
    const float* gather = (const float*)d_in[0];
    const float* cv     = (const float*)d_in[1];
    const float* VMM    = (const float*)d_in[2];
    const float* w1  = (const float*)d_in[3];
    const float* g1  = (const float*)d_in[5];
    const float* be1 = (const float*)d_in[6];
    const float* w2  = (const float*)d_in[7];
    const float* b2  = (const float*)d_in[8];
    const float* g2  = (const float*)d_in[9];
    const float* be2 = (const float*)d_in[10];
    const float* w3  = (const float*)d_in[11];
    const float* b3  = (const float*)d_in[12];
    const float* g3  = (const float*)d_in[13];
    const float* be3 = (const float*)d_in[14];
    const float* wf  = (const float*)d_in[15];
    const float* bf  = (const float*)d_in[16];
    const float* gf  = (const float*)d_in[17];
    const float* bef = (const float*)d_in[18];
    float* out = (float*)d_out;

    k_init<<<1, 64>>>();
    k_conv1<<<MM*NS1, 256>>>(gather, w1);
    k_conv2<<<MM*NS2, 256>>>(w2, b2, g1, be1);
    k_conv3<<<(N3 + 127)/128, 128>>>(w3, b3, g2, be2);
    k_mid<<<MM*4, 256>>>(cv, VMM, g3, be3);
    k_statsF<<<BSZ*(RHH/TROWS), 256>>>(wf, bf);
    k_final<<<NF/4/256, 256>>>(gf, bef, out);
}

// round 13
// speedup vs baseline: 1.6663x; 1.6663x over previous
#include <cuda_runtime.h>
#include <math.h>

#define BSZ  8
#define KPS  8
#define NPK  16
#define TT   3072
#define WGW  64
#define HHH  256
#define WCC  256
#define RHH  1024
#define RWW  512
#define MM   64          // BSZ*KPS

#define C1H 1024
#define C1W 31
#define C2H 341
#define C2W 15
#define C3H 113
#define C3W 7

#define N1  (MM*C1H*C1W)     // 2031616
#define N2  (MM*C2H*C2W)     // 327360 per channel
#define N3  (MM*C3H*C3W)     // 50624
#define NF  (BSZ*RHH*RWW)    // 4194304

#define TROWS 16             // output rows per tile in the final stage

// conv1 tiling
#define S1ROWS 32
#define S1IN   (3*S1ROWS)    // 96
#define NS1    (C1H/S1ROWS)  // 32

// conv2 tiling
#define R2   22
#define NS2  16
#define TR2  (3*R2 + 4)      // 70

// ---------------- scratch (device globals; no allocation) ----------------
__device__ unsigned int g_maxbits;
__device__ double g_s1, g_q1;
__device__ double g_s2[2], g_q2[2];
__device__ double g_s3, g_q3;
__device__ double g_sf, g_qf;

__device__ float g_conv1[N1];
__device__ float g_conv2[2*N2];
__device__ float g_conv3[N3];
__device__ float g_yraw[NF];

// ---------------- helpers ----------------
__device__ __forceinline__ float lrelu(float x){ return x >= 0.f ? x : 0.1f*x; }

__device__ __forceinline__ float warpSumF(float v){
#pragma unroll
    for (int o = 16; o > 0; o >>= 1) v += __shfl_down_sync(0xffffffffu, v, o);
    return v;
}
__device__ __forceinline__ float warpMaxF(float v){
#pragma unroll
    for (int o = 16; o > 0; o >>= 1) v = fmaxf(v, __shfl_down_sync(0xffffffffu, v, o));
    return v;
}

// 256-thread block reduction of (a,b) -> double atomics
__device__ __forceinline__ void blockRedAdd2(float a, float b, double* da, double* db){
    a = warpSumF(a); b = warpSumF(b);
    __shared__ double sa[8], sb[8];
    int lane = threadIdx.x & 31, w = threadIdx.x >> 5;
    if (lane == 0){ sa[w] = (double)a; sb[w] = (double)b; }
    __syncthreads();
    if (w == 0){
        double x = (lane < 8) ? sa[lane] : 0.0;
        double y = (lane < 8) ? sb[lane] : 0.0;
#pragma unroll
        for (int o = 4; o > 0; o >>= 1){
            x += __shfl_down_sync(0xffffffffu, x, o);
            y += __shfl_down_sync(0xffffffffu, y, o);
        }
        if (lane == 0){ atomicAdd(da, x); atomicAdd(db, y); }
    }
    __syncthreads();
}

// 128-thread variant
__device__ __forceinline__ void blockRedAdd2_128(float a, float b, double* da, double* db){
    a = warpSumF(a); b = warpSumF(b);
    __shared__ double sa[4], sb[4];
    int lane = threadIdx.x & 31, w = threadIdx.x >> 5;
    if (lane == 0){ sa[w] = (double)a; sb[w] = (double)b; }
    __syncthreads();
    if (w == 0){
        double x = (lane < 4) ? sa[lane] : 0.0;
        double y = (lane < 4) ? sb[lane] : 0.0;
#pragma unroll
        for (int o = 2; o > 0; o >>= 1){
            x += __shfl_down_sync(0xffffffffu, x, o);
            y += __shfl_down_sync(0xffffffffu, y, o);
        }
        if (lane == 0){ atomicAdd(da, x); atomicAdd(db, y); }
    }
    __syncthreads();
}

// ---------------- kernels ----------------
__global__ void k_init(){
    g_maxbits = 0u;
    g_s1 = 0; g_q1 = 0;
    g_s2[0] = 0; g_s2[1] = 0; g_q2[0] = 0; g_q2[1] = 0;
    g_s3 = 0; g_q3 = 0;
    g_sf = 0; g_qf = 0;
}

// smem-tiled conv1 RAW + maxabs + stats. Block = image m x 32-output-row strip.
__global__ void __launch_bounds__(256) k_conv1(const float* __restrict__ g,
                                               const float* __restrict__ w1){
    __shared__ float s_in[S1IN][WGW];   // 24 KB

    int m     = blockIdx.x >> 5;
    int strip = blockIdx.x & 31;
    int i0    = strip * S1ROWS;
    int tid   = threadIdx.x;

    const float4* src = (const float4*)(g + (size_t)m*(TT*WGW) + (size_t)(3*i0)*WGW);

    float mx = 0.f;
#pragma unroll
    for (int k = 0; k < (S1IN*16)/256; k++){
        int idx = tid + k*256;
        float4 v = src[idx];
        int row = idx >> 4, c4 = idx & 15;
        s_in[row][c4*4+0] = v.x;
        s_in[row][c4*4+1] = v.y;
        s_in[row][c4*4+2] = v.z;
        s_in[row][c4*4+3] = v.w;
        mx = fmaxf(mx, fmaxf(fmaxf(fabsf(v.x), fabsf(v.y)), fmaxf(fabsf(v.z), fabsf(v.w))));
    }
    __syncthreads();

    float w[9];
#pragma unroll
    for (int p = 0; p < 9; p++) w[p] = __ldg(&w1[p]);

    float s = 0.f, q = 0.f;
    for (int o = tid; o < S1ROWS*C1W; o += 256){
        int oi = o / C1W, j = o % C1W;
        int r0 = 3*oi, c0 = 2*j;
        float acc = 0.f;
#pragma unroll
        for (int p = 0; p < 3; p++){
            acc += w[p*3+0]*s_in[r0+p][c0]
                 + w[p*3+1]*s_in[r0+p][c0+1]
                 + w[p*3+2]*s_in[r0+p][c0+2];
        }
        g_conv1[((size_t)m*C1H + i0 + oi)*C1W + j] = acc;
        s += acc; q += acc*acc;
    }

    {
        float mm = warpMaxF(mx);
        __shared__ float sm[8];
        int lane = threadIdx.x & 31, wp = threadIdx.x >> 5;
        if (lane == 0) sm[wp] = mm;
        __syncthreads();
        if (wp == 0){
            mm = (lane < 8) ? sm[lane] : 0.f;
            mm = warpMaxF(mm);
            if (lane == 0) atomicMax(&g_maxbits, __float_as_uint(mm));
        }
        __syncthreads();
    }
    blockRedAdd2(s, q, &g_s1, &g_q1);
}

// smem-tiled conv2 (separable pooling)
__global__ void __launch_bounds__(256) k_conv2(const float* __restrict__ w2,
                                               const float* __restrict__ b2,
                                               const float* __restrict__ g1,
                                               const float* __restrict__ be1){
    __shared__ float s_act[TR2][36];
    __shared__ float s_rm3[TR2][32];
    __shared__ float s_rm5[TR2][32];
    __shared__ float s_ab[2];

    int m     = blockIdx.x >> 4;
    int strip = blockIdx.x & 15;
    int i0    = strip * R2;
    int nout  = min(R2, C2H - i0);
    int tid   = threadIdx.x;

    if (tid == 0){
        double inv  = 1.0 / (double)__uint_as_float(g_maxbits);
        double mc   = g_s1 / (double)N1;
        double varc = g_q1 / (double)N1 - mc*mc;
        double istd = 1.0 / sqrt(inv*inv*varc + 1e-5);
        double A = inv*istd*(double)g1[0];
        s_ab[0] = (float)A;
        s_ab[1] = (float)((double)be1[0] - A*mc);
    }
    for (int lr = tid; lr < TR2; lr += 256){
        s_act[lr][0] = -1e30f; s_act[lr][1] = -1e30f;
        s_act[lr][33] = -1e30f; s_act[lr][34] = -1e30f;
    }
    __syncthreads();
    float A1 = s_ab[0], B1 = s_ab[1];

    int gr0 = 3*i0 - 2;
    const float* src = g_conv1 + (size_t)m*(C1H*C1W);
    for (int idx = tid; idx < TR2*C1W; idx += 256){
        int lr = idx / C1W, c = idx % C1W;
        int gr = gr0 + lr;
        float v = -1e30f;
        if (gr >= 0 && gr < C1H)
            v = lrelu(src[gr*C1W + c]*A1 + B1);
        s_act[lr][c+2] = v;
    }
    __syncthreads();

    for (int idx = tid; idx < TR2*C1W; idx += 256){
        int lr = idx / C1W, c = idx % C1W;
        float a0 = s_act[lr][c],   a1 = s_act[lr][c+1], a2 = s_act[lr][c+2];
        float a3 = s_act[lr][c+3], a4 = s_act[lr][c+4];
        s_rm3[lr][c] = fmaxf(a1, fmaxf(a2, a3));
        s_rm5[lr][c] = fmaxf(fmaxf(a0, a1), fmaxf(a2, fmaxf(a3, a4)));
    }
    __syncthreads();

    float w[54];
#pragma unroll
    for (int p = 0; p < 54; p++) w[p] = __ldg(&w2[p]);
    float bb0 = __ldg(&b2[0]), bb1 = __ldg(&b2[1]);

    float s0 = 0.f, q0 = 0.f, s1 = 0.f, q1 = 0.f;
    for (int o = tid; o < nout*C2W; o += 256){
        int oi = o / C2W, j = o % C2W;
        float acc0 = bb0, acc1 = bb1;
#pragma unroll
        for (int p = 0; p < 3; p++){
            int lr = 3*oi + p + 2;
#pragma unroll
            for (int qq = 0; qq < 3; qq++){
                int c = 2*j + qq;
                float v0 = s_act[lr][c+2];
                float p3 = fmaxf(s_rm3[lr-1][c], fmaxf(s_rm3[lr][c], s_rm3[lr+1][c]));
                float p5 = fmaxf(fmaxf(s_rm5[lr-2][c], s_rm5[lr-1][c]),
                                 fmaxf(s_rm5[lr][c], fmaxf(s_rm5[lr+1][c], s_rm5[lr+2][c])));
                int off = p*3 + qq;
                acc0 += w[off]*v0    + w[9+off]*p3  + w[18+off]*p5;
                acc1 += w[27+off]*v0 + w[36+off]*p3 + w[45+off]*p5;
            }
        }
        int i = i0 + oi;
        g_conv2[((m*2+0)*C2H + i)*C2W + j] = acc0;
        g_conv2[((m*2+1)*C2H + i)*C2W + j] = acc1;
        s0 += acc0; q0 += acc0*acc0;
        s1 += acc1; q1 += acc1*acc1;
    }
    blockRedAdd2(s0, q0, &g_s2[0], &g_q2[0]);
    blockRedAdd2(s1, q1, &g_s2[1], &g_q2[1]);
}

// conv3: per-output, 128-thread blocks (round-8 proven form)
__global__ void __launch_bounds__(128) k_conv3(const float* __restrict__ w3,
                                               const float* __restrict__ b3,
                                               const float* __restrict__ g2,
                                               const float* __restrict__ be2){
    __shared__ float s_ab[4];
    if (threadIdx.x < 2){
        int c = threadIdx.x;
        double mn = g_s2[c] / (double)N2;
        double vr = g_q2[c] / (double)N2 - mn*mn;
        double sc = (double)g2[c] / sqrt(vr + 1e-5);
        s_ab[c]   = (float)sc;
        s_ab[2+c] = (float)((double)be2[c] - mn*sc);
    }
    __syncthreads();

    int idx = blockIdx.x*blockDim.x + threadIdx.x;
    float s = 0, q = 0;
    if (idx < N3){
        int j = idx % C3W; int t = idx / C3W; int i = t % C3H; int m = t / C3H;
        float acc = b3[0];
#pragma unroll
        for (int c = 0; c < 2; c++){
            float A2 = s_ab[c], B2 = s_ab[2+c];
            const float* B = g_conv2 + ((m*2+c)*C2H)*C2W;
#pragma unroll
            for (int p = 0; p < 3; p++){
#pragma unroll
                for (int qq = 0; qq < 2; qq++){
                    float raw = B[(3*i+p)*C2W + 2*j+qq];
                    acc += w3[c*6 + p*2 + qq]*lrelu(raw*A2 + B2);
                }
            }
        }
        g_conv3[idx] = acc;
        s = acc; q = acc*acc;
    }
    blockRedAdd2_128(s, q, &g_s3, &g_q3);
}

// rowval for (m, h) from conv3 with BN3 affine
__device__ __forceinline__ float rowval_at(int m, int h, float A3, float B3){
    const float wcol[7] = {4.f/37.f, 5.f/37.f, 6.f/37.f, 7.f/37.f, 6.f/37.f, 5.f/37.f, 4.f/37.f};
    const float* B = g_conv3 + ((size_t)m*C3H + h)*C3W;
    float rv = 0.f;
#pragma unroll
    for (int j = 0; j < 7; j++)
        rv += wcol[j] * lrelu(B[j]*A3 + B3);
    return rv;
}

// vint for (m, h): piecewise-linear interp of cv curve
__device__ __forceinline__ int vint_at(const float* __restrict__ cv,
                                       const float* __restrict__ VMM,
                                       int m, int h){
    int b = m / KPS;
    const float* C = cv + m*NPK*2;
    const float dt = 7000.0f/255.0f;
    float vm0 = VMM[b*2];
    float dv = (VMM[b*2+1] - vm0)/255.0f;
    float tq = (float)h;
    float tp = C[0]/dt, vp = (C[1] - vm0)/dv;
    float val;
    if (tq <= tp){
        val = vp;
    } else {
        val = (C[2*(NPK-1)+1] - vm0)/dv;
        for (int n = 1; n < NPK; n++){
            float tn = C[2*n]/dt, vn = (C[2*n+1] - vm0)/dv;
            if (tq <= tn){ val = vp + (vn - vp)*(tq - tp)/(tn - tp); break; }
            tp = tn; vp = vn;
        }
    }
    int vi = (int)val;
    return min(WCC-1, max(0, vi));
}

// sparse scatter of one source column v with weight w into mix row
__device__ __forceinline__ void scatter_src(float* row, int v, float w){
    if (w == 0.f) return;
    if (v == 0){
        atomicAdd(&row[0], w);
        atomicAdd(&row[1], 0.75f*w);
        atomicAdd(&row[2], 0.25f*w);
    } else if (v == 255){
        atomicAdd(&row[509], 0.25f*w);
        atomicAdd(&row[510], 0.75f*w);
        atomicAdd(&row[511], w);
    } else {
        atomicAdd(&row[2*v-1], 0.25f*w);
        atomicAdd(&row[2*v  ], 0.75f*w);
        atomicAdd(&row[2*v+1], 0.75f*w);
        atomicAdd(&row[2*v+2], 0.25f*w);
    }
}

// fused genr/vint + mix (sparse) + conv_f: raw y + stats. k_mid is gone.
__global__ void __launch_bounds__(256) k_statsF(const float* __restrict__ cv,
                                                const float* __restrict__ VMM,
                                                const float* __restrict__ g3,
                                                const float* __restrict__ be3,
                                                const float* __restrict__ wf,
                                                const float* __restrict__ bf){
    __shared__ float s_mix[TROWS+2][RWW];
    __shared__ float s_g[TROWS+2][8];
    __shared__ float s_w0[TROWS+2][8];
    __shared__ float s_w1[TROWS+2][8];
    __shared__ int   s_v0[TROWS+2][8];
    __shared__ int   s_v1[TROWS+2][8];
    __shared__ float s_base[TROWS+2];
    __shared__ float s_ab[2];

    int b   = blockIdx.x / (RHH/TROWS);
    int rh0 = (blockIdx.x % (RHH/TROWS)) * TROWS;
    int tid = threadIdx.x;

    if (tid == 0){
        double mn = g_s3 / (double)N3;
        double vr = g_q3 / (double)N3 - mn*mn;
        double sc = (double)g3[0] / sqrt(vr + 1e-5);
        s_ab[0] = (float)sc;
        s_ab[1] = (float)((double)be3[0] - mn*sc);
    }
    __syncthreads();
    float A3 = s_ab[0], B3 = s_ab[1];

    if (tid < (TROWS+2)*8){
        int r = tid >> 3, k = tid & 7;
        int gr = rh0 - 1 + r;
        float g = 0.f, fh = 0.f; int v0 = 0, v1 = 0;
        if (gr >= 0 && gr < RHH){
            int m = b*KPS + k;
            // genr: bilinear of rowval over the 113-row grid
            float ih = (gr + 0.5f)*(113.0f/1024.0f) - 0.5f;
            ih = fminf(fmaxf(ih, 0.f), 112.f);
            int hh0 = (int)ih; float f = ih - (float)hh0;
            int hh1 = min(hh0 + 1, 112);
            g = (1.f - f)*rowval_at(m, hh0, A3, B3) + f*rowval_at(m, hh1, A3, B3);
            // mask rows
            float ihm = (gr + 0.5f)*0.25f - 0.5f;
            ihm = fminf(fmaxf(ihm, 0.f), 255.f);
            int h0 = (int)ihm; fh = ihm - (float)h0; int h1 = min(h0 + 1, 255);
            v0 = vint_at(cv, VMM, m, h0);
            v1 = vint_at(cv, VMM, m, h1);
        }
        s_g[r][k] = g;
        s_w0[r][k] = 0.9f*g*(1.f - fh);
        s_w1[r][k] = 0.9f*g*fh;
        s_v0[r][k] = v0; s_v1[r][k] = v1;
    }
    __syncthreads();

    if (tid < TROWS+2){
        float s = 0.f;
#pragma unroll
        for (int k = 0; k < 8; k++) s += s_g[tid][k];
        s_base[tid] = 0.01f*s;
    }
    __syncthreads();

    for (int idx = tid; idx < (TROWS+2)*RWW; idx += 256){
        int r = idx >> 9, c = idx & 511;
        s_mix[r][c] = s_base[r];
    }
    __syncthreads();

    if (tid < (TROWS+2)*8){
        int r = tid >> 3, k = tid & 7;
        scatter_src(&s_mix[r][0], s_v0[r][k], s_w0[r][k]);
        scatter_src(&s_mix[r][0], s_v1[r][k], s_w1[r][k]);
    }
    __syncthreads();

    float W[9];
#pragma unroll
    for (int i = 0; i < 9; i++) W[i] = __ldg(&wf[i]);
    float bb = __ldg(&bf[0]);

    float s = 0.f, q = 0.f;
    for (int orow = 0; orow < TROWS; orow++){
#pragma unroll
        for (int half = 0; half < 2; half++){
            int c = tid + half*256;
            float acc = bb;
#pragma unroll
            for (int p = 0; p < 3; p++){
#pragma unroll
                for (int qq = 0; qq < 3; qq++){
                    int cc = c - 1 + qq;
                    if (cc >= 0 && cc < RWW)
                        acc += W[p*3+qq]*s_mix[orow+p][cc];
                }
            }
            g_yraw[((size_t)b*RHH + rh0 + orow)*RWW + c] = acc;
            s += acc; q += acc*acc;
        }
    }
    blockRedAdd2(s, q, &g_sf, &g_qf);
}

// elementwise: out = lrelu(yraw*sc + sh), float4
__global__ void __launch_bounds__(256) k_final(const float* __restrict__ gf,
                                               const float* __restrict__ bef,
                                               float* __restrict__ out){
    __shared__ float s_ab[2];
    if (threadIdx.x == 0){
        double mn = g_sf / (double)NF;
        double vr = g_qf / (double)NF - mn*mn;
        double sc = (double)gf[0] / sqrt(vr + 1e-5);
        s_ab[0] = (float)sc;
        s_ab[1] = (float)((double)bef[0] - mn*sc);
    }
    __syncthreads();
    float sc = s_ab[0], sh = s_ab[1];

    int i = blockIdx.x*blockDim.x + threadIdx.x;
    if (i < NF/4){
        float4 y = ((const float4*)g_yraw)[i];
        float4 o;
        o.x = lrelu(y.x*sc + sh);
        o.y = lrelu(y.y*sc + sh);
        o.z = lrelu(y.z*sc + sh);
        o.w = lrelu(y.w*sc + sh);
        ((float4*)out)[i] = o;
    }
}

// ---------------- launch ----------------
extern "C" void kernel_launch(void* const* d_in, const int* in_sizes, int n_in,
                              void* d_out, int out_size){
    const float* gather = (const float*)d_in[0];
    const float* cv     = (const float*)d_in[1];
    const float* VMM    = (const float*)d_in[2];
    const float* w1  = (const float*)d_in[3];
    const float* g1  = (const float*)d_in[5];
    const float* be1 = (const float*)d_in[6];
    const float* w2  = (const float*)d_in[7];
    const float* b2  = (const float*)d_in[8];
    const float* g2  = (const float*)d_in[9];
    const float* be2 = (const float*)d_in[10];
    const float* w3  = (const float*)d_in[11];
    const float* b3  = (const float*)d_in[12];
    const float* g3  = (const float*)d_in[13];
    const float* be3 = (const float*)d_in[14];
    const float* wf  = (const float*)d_in[15];
    const float* bf  = (const float*)d_in[16];
    const float* gf  = (const float*)d_in[17];
    const float* bef = (const float*)d_in[18];
    float* out = (float*)d_out;

    k_init<<<1, 1>>>();
    k_conv1<<<MM*NS1, 256>>>(gather, w1);
    k_conv2<<<MM*NS2, 256>>>(w2, b2, g1, be1);
    k_conv3<<<(N3 + 127)/128, 128>>>(w3, b3, g2, be2);
    k_statsF<<<BSZ*(RHH/TROWS), 256>>>(cv, VMM, g3, be3, wf, bf);
    k_final<<<NF/4/256, 256>>>(gf, bef, out);
}